// round 7
// baseline (speedup 1.0000x reference)
#include <cuda_runtime.h>
#include <cuda_bf16.h>

// HamiltonianLinearFlow: out[t,n,:] = expm( c_n*t_t*(J@A) ) @ x_n
//   A = sym(M+M0) 16x16; J=[[0,I],[-I,0]] => (JA)[i][:] = sgn_i * A[i^8][:],
//   sgn_i = +1 (i<8), -1 (i>=8).
// out = x + sum_{k=1..6} (c t)^k v_k,  v_k = (JA)^k x / k!   (KT=6: trunc ~<1e-7)
// Latency-optimized: ONE barrier; Krylov recurrence in registers via warp
// shuffles (no G matrices, no smem matmul chain); tanh off critical path
// (c folds into tau at Horner time). Warp = 2 samples x 16-lane groups,
// warps split the 32 t-points in halves (chain duplicated across t-halves).

#define MDIM 16
#define TPTS 32
#define KT 6
#define NTHR 256
#define SPB 8          // samples per block (8 warps: 4 sample-pairs x 2 t-halves)
#define ASTR 20        // A_sh row stride (80B: aligned + conflict-free LDS.128)

__global__ __launch_bounds__(NTHR)
void ham_kernel(const float* __restrict__ x,
                const float* __restrict__ tt,
                const float* __restrict__ Mm,
                const float* __restrict__ M0,
                float* __restrict__ out,
                int N)
{
    __shared__ float A_sh[MDIM][ASTR];

    const int tid  = threadIdx.x;
    const int w    = tid >> 5;
    const int lane = tid & 31;
    const int seg  = lane & 16;            // 16-lane group base
    const int i    = lane & 15;            // component index
    const int thalf = w >> 2;              // 0: t=0..15, 1: t=16..31
    const int n    = blockIdx.x * SPB + ((w & 3) << 1) + (lane >> 4);

    // ---- cooperative A = sym(M+M0) (only smem use; ONE barrier) ----
    {
        int ai = tid >> 4, aj = tid & 15;
        A_sh[ai][aj] = 0.5f * ((Mm[ai * 16 + aj] + M0[ai * 16 + aj]) +
                               (Mm[aj * 16 + ai] + M0[aj * 16 + ai]));
    }

    // ---- per-thread loads issued before the barrier (latency overlap) ----
    float xr[MDIM];
    {
        const float4* xp = (const float4*)(x + (size_t)n * MDIM);
        float4 q0 = __ldg(xp+0), q1 = __ldg(xp+1), q2 = __ldg(xp+2), q3 = __ldg(xp+3);
        xr[0]=q0.x; xr[1]=q0.y; xr[2]=q0.z; xr[3]=q0.w;
        xr[4]=q1.x; xr[5]=q1.y; xr[6]=q1.z; xr[7]=q1.w;
        xr[8]=q2.x; xr[9]=q2.y; xr[10]=q2.z; xr[11]=q2.w;
        xr[12]=q3.x; xr[13]=q3.y; xr[14]=q3.z; xr[15]=q3.w;
    }
    float tv[16];
    {
        const float4* tp = (const float4*)(tt + thalf * 16);
        float4 q0 = __ldg(tp+0), q1 = __ldg(tp+1), q2 = __ldg(tp+2), q3 = __ldg(tp+3);
        tv[0]=q0.x; tv[1]=q0.y; tv[2]=q0.z; tv[3]=q0.w;
        tv[4]=q1.x; tv[5]=q1.y; tv[6]=q1.z; tv[7]=q1.w;
        tv[8]=q2.x; tv[9]=q2.y; tv[10]=q2.z; tv[11]=q2.w;
        tv[12]=q3.x; tv[13]=q3.y; tv[14]=q3.z; tv[15]=q3.w;
    }
    __syncthreads();

    // ---- jrow = sgn_i * A[i^8][:]  (JA row i), conflict-free LDS.128 ----
    float jr[MDIM];
    {
        const int r = i ^ 8;
        const float4* ap = (const float4*)&A_sh[r][0];
        float4 q0 = ap[0], q1 = ap[1], q2 = ap[2], q3 = ap[3];
        const float sg = (i < 8) ? 1.f : -1.f;
        jr[0]=sg*q0.x; jr[1]=sg*q0.y; jr[2]=sg*q0.z; jr[3]=sg*q0.w;
        jr[4]=sg*q1.x; jr[5]=sg*q1.y; jr[6]=sg*q1.z; jr[7]=sg*q1.w;
        jr[8]=sg*q2.x; jr[9]=sg*q2.y; jr[10]=sg*q2.z; jr[11]=sg*q2.w;
        jr[12]=sg*q3.x; jr[13]=sg*q3.y; jr[14]=sg*q3.z; jr[15]=sg*q3.w;
    }

    // dot helper: 4 partial accumulators (short FMA chains)
    auto dotv = [&](const float* v) -> float {
        float a0 = jr[0]*v[0] + jr[1]*v[1] + jr[2]*v[2] + jr[3]*v[3];
        float a1 = jr[4]*v[4] + jr[5]*v[5] + jr[6]*v[6] + jr[7]*v[7];
        float a2 = jr[8]*v[8] + jr[9]*v[9] + jr[10]*v[10] + jr[11]*v[11];
        float a3 = jr[12]*v[12] + jr[13]*v[13] + jr[14]*v[14] + jr[15]*v[15];
        return (a0 + a1) + (a2 + a3);
    };

    // ---- v1 = JA x;  H from the same dots (off critical path) ----
    float vk[KT];
    vk[0] = dotv(xr);                       // v1_i = (JA x)_i = d_i

    // H = sum_m x_m (Ax)_m ;  (Ax)_{i^8} = sgn_i * d_i
    float h = xr[i ^ 8] * ((i < 8) ? vk[0] : -vk[0]);
    #pragma unroll
    for (int off = 8; off; off >>= 1)
        h += __shfl_xor_sync(0xffffffffu, h, off);
    const float c = 1.0f + 0.01f * tanhf(h);   // overlaps the levels below

    // ---- Krylov levels 2..6: gather v via shuffles, dot in registers ----
    const float rk[KT] = {1.f, 0.5f, 1.f/3.f, 0.25f, 0.2f, 1.f/6.f};
    float vcur = vk[0];
    #pragma unroll
    for (int k = 1; k < KT; k++) {
        float vv[MDIM];
        #pragma unroll
        for (int j = 0; j < MDIM; j++)
            vv[j] = __shfl_sync(0xffffffffu, vcur, seg | j);
        vcur = dotv(vv) * rk[k];
        vk[k] = vcur;
    }

    // ---- Horner over this warp's 16 t-points; coalesced scalar stores ----
    const float xv = xr[i];
    const size_t plane = (size_t)N * MDIM;
    float* op = out + (size_t)(thalf * 16) * plane + (size_t)n * MDIM + i;
    #pragma unroll
    for (int u = 0; u < 16; u++) {
        const float tau = c * tv[u];
        float a = vk[KT - 1];
        #pragma unroll
        for (int k = KT - 2; k >= 0; k--) a = fmaf(tau, a, vk[k]);
        op[(size_t)u * plane] = fmaf(tau, a, xv);
    }
}

extern "C" void kernel_launch(void* const* d_in, const int* in_sizes, int n_in,
                              void* d_out, int out_size) {
    const float* x  = (const float*)d_in[0];   // (N, 16)
    const float* tt = (const float*)d_in[1];   // (32,)
    const float* Mm = (const float*)d_in[2];   // (16,16)
    const float* M0 = (const float*)d_in[4];   // (16,16)  (J exploited algebraically)
    float* out = (float*)d_out;                // (32, N, 16)

    const int N = in_sizes[0] / MDIM;          // 2048
    const int blocks = (N + SPB - 1) / SPB;    // 256
    ham_kernel<<<blocks, NTHR>>>(x, tt, Mm, M0, out, N);
}